// round 3
// baseline (speedup 1.0000x reference)
#include <cuda_runtime.h>

// ---------------------------------------------------------------------------
// CubeMoveHead: only the first MC=64 cube-nodes per batch contribute to the
// output, so we select those <=32768 nodes first and run the MLP only on them.
// ---------------------------------------------------------------------------

#define D 128
#define G 128
#define H 128
#define MC 64
#define MV 24
#define NEGV (-1000000000.0f)

#define MAXB 1024  // upper bound on batch size for static scratch

__device__ int g_segStart[MAXB + 1];
__device__ int g_sel[MAXB * MC];
__device__ int g_validCount[MAXB];
__device__ int g_maskIsBool[2];  // [0] cube_mask, [1] move_mask

// ---------------------------------------------------------------------------
// Detect whether the bool-ish inputs are stored as 1-byte bools or int32.
// int32 0/1 values have zero bytes at all offsets with (off & 3) != 0.
// 1-byte bools (random 0/1) have ~50% nonzero bytes there. Checking 3 KB of
// misaligned bytes makes a false negative probability ~2^-1500.
// ---------------------------------------------------------------------------
__global__ void k_detect(const unsigned char* __restrict__ cm,
                         const unsigned char* __restrict__ mv) {
    int tid = threadIdx.x;
    int f0 = 0, f1 = 0;
    for (int i = tid; i < 4096; i += 256) {
        if ((i & 3) != 0) {
            f0 |= cm[i];
            f1 |= mv[i];
        }
    }
    int r0 = __syncthreads_or(f0);
    int r1 = __syncthreads_or(f1);
    if (tid == 0) {
        g_maskIsBool[0] = (r0 != 0);
        g_maskIsBool[1] = (r1 != 0);
    }
}

// ---------------------------------------------------------------------------
// Batch is sorted: segment start of batch b = lower_bound(batch, b).
// One thread per boundary value 0..B (inclusive).
// ---------------------------------------------------------------------------
__global__ void k_segstart(const int* __restrict__ batch, int n, int B) {
    int v = blockIdx.x * blockDim.x + threadIdx.x;
    if (v > B) return;
    int lo = 0, hi = n;
    while (lo < hi) {
        int mid = (lo + hi) >> 1;
        if (batch[mid] < v) lo = mid + 1; else hi = mid;
    }
    g_segStart[v] = lo;
}

// ---------------------------------------------------------------------------
// One block per batch. Scan the segment in 256-wide strips; ballot+popc gives
// deterministic, node-order cube ranks. Record node index of first MC cubes.
// ---------------------------------------------------------------------------
__global__ void k_select(const int* __restrict__ cm_i,
                         const unsigned char* __restrict__ cm_b) {
    int b = blockIdx.x;
    int start = g_segStart[b], end = g_segStart[b + 1];
    int isb = g_maskIsBool[0];

    __shared__ int s_wcnt[8];
    __shared__ int s_base;
    int tid = threadIdx.x, lane = tid & 31, w = tid >> 5;
    if (tid == 0) s_base = 0;
    __syncthreads();

    for (int it = start; it < end; it += 256) {
        if (s_base >= MC) break;  // uniform: s_base is shared, stable after sync
        int i = it + tid;
        int c = 0;
        if (i < end) c = isb ? (cm_b[i] != 0) : (cm_i[i] != 0);
        unsigned mm = __ballot_sync(0xffffffffu, c);
        if (lane == 0) s_wcnt[w] = __popc(mm);
        __syncthreads();
        int pre = 0, tot = 0;
#pragma unroll
        for (int ww = 0; ww < 8; ww++) {
            int v = s_wcnt[ww];
            if (ww < w) pre += v;
            tot += v;
        }
        if (c) {
            int rank = s_base + pre + __popc(mm & ((1u << lane) - 1u));
            if (rank < MC) g_sel[b * MC + rank] = i;
        }
        __syncthreads();
        if (tid == 0) s_base += tot;
        __syncthreads();
    }
    // All threads exit uniformly; s_base was last written by thread 0 after a
    // barrier in which everyone participated.
    if (tid == 0) g_validCount[b] = (s_base < MC) ? s_base : MC;
}

// ---------------------------------------------------------------------------
// MLP over the selected slots. 32 slots/block (all in the same batch since
// MC=64 and 32 | 64). 256 threads.
//   layer 1: thread = (h-unit t = tid&127, slot-group g = tid>>7 of 16 slots)
//            16 register accumulators; W1 column loads coalesced across the
//            warp and L1-resident (128 KB); combined read via broadcast LDS.128
//   layer 2: 768 dot-128 products, 3 per thread
//   epilogue: fused validity + move_mask -> NEG
// ---------------------------------------------------------------------------
#define COMB_LD 260   // 256 + 4 pad (keeps float4 alignment: 260*4 % 16 == 0)
#define H_LD 132      // 128 + 4 pad

__global__ __launch_bounds__(256) void k_mlp(
    const float* __restrict__ nf, const float* __restrict__ gf,
    const float* __restrict__ W1, const float* __restrict__ b1,
    const float* __restrict__ W2, const float* __restrict__ b2,
    const int* __restrict__ mv_i, const unsigned char* __restrict__ mv_b,
    float* __restrict__ out) {
    __shared__ float s_comb[32 * COMB_LD];  // 33.3 KB; reused for h after layer 1
    __shared__ int s_sel[32];
    __shared__ int s_vc;

    int tid = threadIdx.x;
    int slot0 = blockIdx.x * 32;
    int b = slot0 >> 6;  // MC = 64 -> whole block is one batch

    if (tid < 32) s_sel[tid] = g_sel[slot0 + tid];
    if (tid == 0) s_vc = g_validCount[b];
    __syncthreads();
    int vc = s_vc;

    // ---- stage combined = [node_features | global_features[b]] ----
    {
        int w = tid >> 5, lane = tid & 31;
        for (int s = w; s < 32; s += 8) {
            int c = (slot0 + s) & (MC - 1);
            float4 v0 = make_float4(0.f, 0.f, 0.f, 0.f);
            float4 v1 = v0;
            if (c < vc) {
                long long node = s_sel[s];
                v0 = *(const float4*)&nf[node * D + lane * 4];
                v1 = *(const float4*)&gf[(long long)b * G + lane * 4];
            }
            *(float4*)&s_comb[s * COMB_LD + lane * 4] = v0;
            *(float4*)&s_comb[s * COMB_LD + D + lane * 4] = v1;
        }
    }
    __syncthreads();

    // ---- layer 1: h = relu(combined @ W1 + b1) ----
    int t = tid & 127;
    int g = tid >> 7;  // 0 or 1: slot group of 16
    const float* cb = &s_comb[g * 16 * COMB_LD];
    float acc[16];
#pragma unroll
    for (int j = 0; j < 16; j++) acc[j] = 0.f;

    for (int k = 0; k < D + G; k += 4) {
        float w0 = W1[(k + 0) * H + t];
        float w1v = W1[(k + 1) * H + t];
        float w2v = W1[(k + 2) * H + t];
        float w3v = W1[(k + 3) * H + t];
#pragma unroll
        for (int j = 0; j < 16; j++) {
            float4 c4 = *(const float4*)&cb[j * COMB_LD + k];
            float a = acc[j];
            a = fmaf(c4.x, w0, a);
            a = fmaf(c4.y, w1v, a);
            a = fmaf(c4.z, w2v, a);
            a = fmaf(c4.w, w3v, a);
            acc[j] = a;
        }
    }
    __syncthreads();  // combined fully consumed; reuse smem for h

    float* s_h = s_comb;  // [32][H_LD] = 16.9 KB, fits inside s_comb
    float bt = b1[t];
#pragma unroll
    for (int j = 0; j < 16; j++) {
        float hv = acc[j] + bt;
        hv = hv > 0.f ? hv : 0.f;
        s_h[(g * 16 + j) * H_LD + t] = hv;
    }
    __syncthreads();

    // ---- layer 2 + masked epilogue ----
    int isb = g_maskIsBool[1];
#pragma unroll
    for (int r = 0; r < 3; r++) {
        int idx = tid + 256 * r;  // 0..767 = 32 slots x 24 moves
        int s = idx / MV;
        int m = idx - s * MV;
        float a2 = b2[m];
#pragma unroll
        for (int k = 0; k < H; k += 4) {
            float4 h4 = *(const float4*)&s_h[s * H_LD + k];
            a2 = fmaf(h4.x, W2[(k + 0) * MV + m], a2);
            a2 = fmaf(h4.y, W2[(k + 1) * MV + m], a2);
            a2 = fmaf(h4.z, W2[(k + 2) * MV + m], a2);
            a2 = fmaf(h4.w, W2[(k + 3) * MV + m], a2);
        }
        int slot = slot0 + s;
        int c = slot & (MC - 1);
        long long oidx = (long long)slot * MV + m;  // == b*MC*MV + c*MV + m
        int mk = isb ? (mv_b[oidx] != 0) : (mv_i[oidx] != 0);
        out[oidx] = (c < vc && mk) ? a2 : NEGV;
    }
}

// ---------------------------------------------------------------------------
extern "C" void kernel_launch(void* const* d_in, const int* in_sizes, int n_in,
                              void* d_out, int out_size) {
    const float* nf = (const float*)d_in[0];        // [N, 128]
    const float* gf = (const float*)d_in[1];        // [B, 128]
    const float* W1 = (const float*)d_in[2];        // [256, 128]
    const float* b1 = (const float*)d_in[3];        // [128]
    const float* W2 = (const float*)d_in[4];        // [128, 24]
    const float* b2 = (const float*)d_in[5];        // [24]
    const void* cm = d_in[6];                       // [N] bool/int32
    const int* batch = (const int*)d_in[7];         // [N] int32
    const void* mv = d_in[8];                       // [B, 64, 24] bool/int32

    int n = in_sizes[7];
    int B = in_sizes[1] / G;
    if (B > MAXB) B = MAXB;

    k_detect<<<1, 256>>>((const unsigned char*)cm, (const unsigned char*)mv);
    k_segstart<<<1, B + 1>>>(batch, n, B);
    k_select<<<B, 256>>>((const int*)cm, (const unsigned char*)cm);
    k_mlp<<<B * 2, 256>>>(nf, gf, W1, b1, W2, b2,
                          (const int*)mv, (const unsigned char*)mv,
                          (float*)d_out);
}

// round 6
// speedup vs baseline: 1.6245x; 1.6245x over previous
#include <cuda_runtime.h>

// ---------------------------------------------------------------------------
// CubeMoveHead: only the first MC=64 cube-nodes per batch contribute to the
// output, so we select those <=32768 nodes first and run the MLP only on them.
// R4: (a) global-half of layer-1 precomputed once per batch (halves FLOPs),
//     (b) 4h x 4slot register tiling in layer-1 (cuts L1/issue overhead 31%->12%).
// ---------------------------------------------------------------------------

#define D 128
#define G 128
#define H 128
#define MC 64
#define MV 24
#define NEGV (-1000000000.0f)

#define MAXB 1024  // upper bound on batch size for static scratch

__device__ int g_segStart[MAXB + 1];
__device__ int g_sel[MAXB * MC];
__device__ int g_validCount[MAXB];
__device__ int g_maskIsBool[2];        // [0] cube_mask, [1] move_mask
__device__ float g_hg[MAXB * H];       // gf[b] @ W1[D:,:] + b1  (per-batch)

// ---------------------------------------------------------------------------
// Detect whether the bool-ish inputs are stored as 1-byte bools or int32.
// int32 0/1 values have zero bytes at all offsets with (off & 3) != 0.
// ---------------------------------------------------------------------------
__global__ void k_detect(const unsigned char* __restrict__ cm,
                         const unsigned char* __restrict__ mv) {
    int tid = threadIdx.x;
    int f0 = 0, f1 = 0;
    for (int i = tid; i < 4096; i += 256) {
        if ((i & 3) != 0) {
            f0 |= cm[i];
            f1 |= mv[i];
        }
    }
    int r0 = __syncthreads_or(f0);
    int r1 = __syncthreads_or(f1);
    if (tid == 0) {
        g_maskIsBool[0] = (r0 != 0);
        g_maskIsBool[1] = (r1 != 0);
    }
}

// ---------------------------------------------------------------------------
// Batch is sorted: segment start of batch b = lower_bound(batch, b).
// ---------------------------------------------------------------------------
__global__ void k_segstart(const int* __restrict__ batch, int n, int B) {
    int v = blockIdx.x * blockDim.x + threadIdx.x;
    if (v > B) return;
    int lo = 0, hi = n;
    while (lo < hi) {
        int mid = (lo + hi) >> 1;
        if (batch[mid] < v) lo = mid + 1; else hi = mid;
    }
    g_segStart[v] = lo;
}

// ---------------------------------------------------------------------------
// Per-batch global-half of layer 1: g_hg[b] = gf[b] @ W1[D:, :] + b1.
// One block per batch, 128 threads (one per hidden unit). W1 rows coalesced.
// ---------------------------------------------------------------------------
__global__ __launch_bounds__(128) void k_global(const float* __restrict__ gf,
                                                const float* __restrict__ W1,
                                                const float* __restrict__ b1) {
    __shared__ float s_g[G];
    int b = blockIdx.x, h = threadIdx.x;
    s_g[h] = gf[b * G + h];
    __syncthreads();
    float a = b1[h];
#pragma unroll 4
    for (int k = 0; k < G; k++)
        a = fmaf(s_g[k], W1[(D + k) * H + h], a);
    g_hg[b * H + h] = a;
}

// ---------------------------------------------------------------------------
// One block per batch. Scan the segment; ballot+popc gives deterministic,
// node-order cube ranks. Record node index of first MC cubes.
// ---------------------------------------------------------------------------
__global__ void k_select(const int* __restrict__ cm_i,
                         const unsigned char* __restrict__ cm_b) {
    int b = blockIdx.x;
    int start = g_segStart[b], end = g_segStart[b + 1];
    int isb = g_maskIsBool[0];

    __shared__ int s_wcnt[8];
    __shared__ int s_base;
    int tid = threadIdx.x, lane = tid & 31, w = tid >> 5;
    if (tid == 0) s_base = 0;
    __syncthreads();

    for (int it = start; it < end; it += 256) {
        if (s_base >= MC) break;  // uniform: shared, stable after sync
        int i = it + tid;
        int c = 0;
        if (i < end) c = isb ? (cm_b[i] != 0) : (cm_i[i] != 0);
        unsigned mm = __ballot_sync(0xffffffffu, c);
        if (lane == 0) s_wcnt[w] = __popc(mm);
        __syncthreads();
        int pre = 0, tot = 0;
#pragma unroll
        for (int ww = 0; ww < 8; ww++) {
            int v = s_wcnt[ww];
            if (ww < w) pre += v;
            tot += v;
        }
        if (c) {
            int rank = s_base + pre + __popc(mm & ((1u << lane) - 1u));
            if (rank < MC) g_sel[b * MC + rank] = i;
        }
        __syncthreads();
        if (tid == 0) s_base += tot;
        __syncthreads();
    }
    if (tid == 0) g_validCount[b] = (s_base < MC) ? s_base : MC;
}

// ---------------------------------------------------------------------------
// MLP over selected slots. 32 slots/block (one batch: MC=64, 32|64), 256 thr.
//   layer 1 (K = D only, global half pre-added via g_hg):
//     thread tile = 4 h-units (h4 = tid&31) x 4 slots (sg = tid>>5)
//     per k-quad: 4 broadcast LDS.128 (slots) + 4 coalesced LDG.128 (W1)
//     -> 64 FMA.  W1[:D] = 64 KB, L1-resident across blocks.
//   layer 2: 768 dot-128, 3 per thread, fused validity+move_mask epilogue.
// ---------------------------------------------------------------------------
#define NF_LD 132   // 128 + 4 pad (keeps float4 alignment, avoids bank dup)

__global__ __launch_bounds__(256) void k_mlp(
    const float* __restrict__ nf,
    const float* __restrict__ W1, const float* __restrict__ W2,
    const float* __restrict__ b2,
    const int* __restrict__ mv_i, const unsigned char* __restrict__ mv_b,
    float* __restrict__ out) {
    __shared__ float s_buf[32 * NF_LD];  // node feats; reused for h after L1
    __shared__ int s_sel[32];
    __shared__ int s_vc;

    int tid = threadIdx.x;
    int slot0 = blockIdx.x * 32;
    int b = slot0 >> 6;  // MC = 64 -> whole block is one batch

    if (tid < 32) s_sel[tid] = g_sel[slot0 + tid];
    if (tid == 0) s_vc = g_validCount[b];
    __syncthreads();
    int vc = s_vc;

    // ---- stage node features [32][128] ----
    {
        int w = tid >> 5, lane = tid & 31;
        for (int s = w; s < 32; s += 8) {
            int c = (slot0 + s) & (MC - 1);
            float4 v0 = make_float4(0.f, 0.f, 0.f, 0.f);
            if (c < vc) {
                long long node = s_sel[s];
                v0 = *(const float4*)&nf[node * D + lane * 4];
            }
            *(float4*)&s_buf[s * NF_LD + lane * 4] = v0;
        }
    }
    __syncthreads();

    // ---- layer 1 ----
    int h4 = tid & 31;   // h-units h4*4 .. h4*4+3 (consecutive across lanes)
    int sg = tid >> 5;   // slots sg*4 .. sg*4+3

    float acc[4][4];     // [jh][js]
    {
        float4 hg4 = *(const float4*)&g_hg[b * H + h4 * 4];
#pragma unroll
        for (int js = 0; js < 4; js++) {
            acc[0][js] = hg4.x;
            acc[1][js] = hg4.y;
            acc[2][js] = hg4.z;
            acc[3][js] = hg4.w;
        }
    }

#pragma unroll 4
    for (int k = 0; k < D; k += 4) {
        float4 wk[4], cs[4];
#pragma unroll
        for (int kk = 0; kk < 4; kk++)
            wk[kk] = *(const float4*)&W1[(k + kk) * H + h4 * 4];
#pragma unroll
        for (int js = 0; js < 4; js++)
            cs[js] = *(const float4*)&s_buf[(sg * 4 + js) * NF_LD + k];
#pragma unroll
        for (int js = 0; js < 4; js++) {
            float4 c = cs[js];
#pragma unroll
            for (int kk = 0; kk < 4; kk++) {
                float cv = (kk == 0) ? c.x : (kk == 1) ? c.y : (kk == 2) ? c.z : c.w;
                float4 w = wk[kk];
                acc[0][js] = fmaf(cv, w.x, acc[0][js]);
                acc[1][js] = fmaf(cv, w.y, acc[1][js]);
                acc[2][js] = fmaf(cv, w.z, acc[2][js]);
                acc[3][js] = fmaf(cv, w.w, acc[3][js]);
            }
        }
    }
    __syncthreads();  // node feats fully consumed; reuse smem for h

    float* s_h = s_buf;  // [32][NF_LD], only [.][0..127] used
#pragma unroll
    for (int js = 0; js < 4; js++) {
        float4 hv;
        hv.x = fmaxf(acc[0][js], 0.f);
        hv.y = fmaxf(acc[1][js], 0.f);
        hv.z = fmaxf(acc[2][js], 0.f);
        hv.w = fmaxf(acc[3][js], 0.f);
        *(float4*)&s_h[(sg * 4 + js) * NF_LD + h4 * 4] = hv;
    }
    __syncthreads();

    // ---- layer 2 + masked epilogue ----
    int isb = g_maskIsBool[1];
#pragma unroll
    for (int r = 0; r < 3; r++) {
        int idx = tid + 256 * r;  // 0..767 = 32 slots x 24 moves
        int s = idx / MV;
        int m = idx - s * MV;
        float a2 = b2[m];
#pragma unroll 8
        for (int k = 0; k < H; k += 4) {
            float4 h4v = *(const float4*)&s_h[s * NF_LD + k];
            a2 = fmaf(h4v.x, W2[(k + 0) * MV + m], a2);
            a2 = fmaf(h4v.y, W2[(k + 1) * MV + m], a2);
            a2 = fmaf(h4v.z, W2[(k + 2) * MV + m], a2);
            a2 = fmaf(h4v.w, W2[(k + 3) * MV + m], a2);
        }
        int slot = slot0 + s;
        int c = slot & (MC - 1);
        long long oidx = (long long)slot * MV + m;  // == b*MC*MV + c*MV + m
        int mk = isb ? (mv_b[oidx] != 0) : (mv_i[oidx] != 0);
        out[oidx] = (c < vc && mk) ? a2 : NEGV;
    }
}

// ---------------------------------------------------------------------------
extern "C" void kernel_launch(void* const* d_in, const int* in_sizes, int n_in,
                              void* d_out, int out_size) {
    const float* nf = (const float*)d_in[0];        // [N, 128]
    const float* gf = (const float*)d_in[1];        // [B, 128]
    const float* W1 = (const float*)d_in[2];        // [256, 128]
    const float* b1 = (const float*)d_in[3];        // [128]
    const float* W2 = (const float*)d_in[4];        // [128, 24]
    const float* b2 = (const float*)d_in[5];        // [24]
    const void* cm = d_in[6];                       // [N] bool/int32
    const int* batch = (const int*)d_in[7];         // [N] int32
    const void* mv = d_in[8];                       // [B, 64, 24] bool/int32

    int n = in_sizes[7];
    int B = in_sizes[1] / G;
    if (B > MAXB) B = MAXB;

    k_detect<<<1, 256>>>((const unsigned char*)cm, (const unsigned char*)mv);
    k_segstart<<<1, B + 1>>>(batch, n, B);
    k_global<<<B, 128>>>(gf, W1, b1);
    k_select<<<B, 256>>>((const int*)cm, (const unsigned char*)cm);
    k_mlp<<<B * 2, 256>>>(nf, W1, W2, b2,
                          (const int*)mv, (const unsigned char*)mv,
                          (float*)d_out);
}

// round 8
// speedup vs baseline: 3.3489x; 2.0615x over previous
#include <cuda_runtime.h>
#include <cuda_bf16.h>
#include <stdint.h>

// ---------------------------------------------------------------------------
// CubeMoveHead R7: select-then-MLP, both layers on mma.sync.m16n8k16 bf16
// (3-pass hi/lo split), weights pre-arranged in HMMA fragment order,
// layer1 C-fragment reused directly as layer2 A-fragment (no smem h).
// 2 kernels: k_prep (detect+segstart+hg+fragment build), k_mlp (select+MLP).
// ---------------------------------------------------------------------------

#define D 128
#define G 128
#define H 128
#define MC 64
#define MV 24
#define NEGV (-1000000000.0f)
#define MAXB 1024

__device__ int   g_segStart[MAXB + 1];
__device__ int   g_maskIsBool[2];       // [0] cube_mask, [1] move_mask
__device__ float g_hg[MAXB * H];        // gf[b] @ W1[D:,:] + b1
__device__ uint4 g_b1frag[4096];        // W1[:D,:] fragments [kc8][nt16][lane32]{bhi0,bhi1,blo0,blo1}
__device__ uint4 g_b2frag[768];         // W2 fragments [kc8][nt3][lane32]

// ---------------------------------------------------------------------------
__device__ __forceinline__ uint32_t pkbf(float lo, float hi) {
    unsigned short l = __bfloat16_as_ushort(__float2bfloat16(lo));
    unsigned short h = __bfloat16_as_ushort(__float2bfloat16(hi));
    return (uint32_t)l | ((uint32_t)h << 16);
}
__device__ __forceinline__ float bfres(float x) {
    return x - __bfloat162float(__float2bfloat16(x));
}
__device__ __forceinline__ void mma16816(float* c, uint32_t a0, uint32_t a1,
                                         uint32_t a2, uint32_t a3,
                                         uint32_t b0, uint32_t b1) {
    asm volatile(
        "mma.sync.aligned.m16n8k16.row.col.f32.bf16.bf16.f32 "
        "{%0,%1,%2,%3}, {%4,%5,%6,%7}, {%8,%9}, {%0,%1,%2,%3};"
        : "+f"(c[0]), "+f"(c[1]), "+f"(c[2]), "+f"(c[3])
        : "r"(a0), "r"(a1), "r"(a2), "r"(a3), "r"(b0), "r"(b1));
}

// ---------------------------------------------------------------------------
// k_prep: block 0 = dtype detect; blocks 1..B = per-batch hg; next 16 = W1
// fragment build; next = W2 fragment build; last = segment starts.
// ---------------------------------------------------------------------------
__global__ __launch_bounds__(256) void k_prep(
    const float* __restrict__ gf, const float* __restrict__ W1,
    const float* __restrict__ b1, const float* __restrict__ W2,
    const unsigned char* __restrict__ cm, const unsigned char* __restrict__ mv,
    const int* __restrict__ batch, int n, int B) {
    int bid = blockIdx.x, tid = threadIdx.x;

    if (bid == 0) {
        // bool(1B) vs int32 detection: int32 0/1 has zero bytes off 4B grid
        int f0 = 0, f1 = 0;
        for (int i = tid; i < 4096; i += 256)
            if (i & 3) { f0 |= cm[i]; f1 |= mv[i]; }
        int r0 = __syncthreads_or(f0);
        int r1 = __syncthreads_or(f1);
        if (tid == 0) { g_maskIsBool[0] = (r0 != 0); g_maskIsBool[1] = (r1 != 0); }
    } else if (bid <= B) {
        __shared__ float s_g[G];
        int b = bid - 1;
        if (tid < G) s_g[tid] = gf[b * G + tid];
        __syncthreads();
        if (tid < H) {
            float a = b1[tid];
#pragma unroll 4
            for (int k = 0; k < G; k++)
                a = fmaf(s_g[k], W1[(D + k) * H + tid], a);
            g_hg[b * H + tid] = a;
        }
    } else {
        int rel = bid - B - 1;
        if (rel < 16) {
            // W1[:D,:] -> m16n8k16 B-fragments (n = h, k = feature)
            int idx = rel * 256 + tid;          // 0..4095
            int lane = idx & 31, nt = (idx >> 5) & 15, kc = idx >> 9;
            int nn = nt * 8 + (lane >> 2);
            int k0 = kc * 16 + (lane & 3) * 2;
            float w00 = W1[(k0 + 0) * H + nn], w01 = W1[(k0 + 1) * H + nn];
            float w10 = W1[(k0 + 8) * H + nn], w11 = W1[(k0 + 9) * H + nn];
            uint4 o;
            o.x = pkbf(w00, w01);                     // bhi0
            o.y = pkbf(w10, w11);                     // bhi1
            o.z = pkbf(bfres(w00), bfres(w01));       // blo0
            o.w = pkbf(bfres(w10), bfres(w11));       // blo1
            g_b1frag[idx] = o;
        } else if (rel == 16) {
            // W2 -> fragments (n = move, k = h)
            for (int idx = tid; idx < 768; idx += 256) {
                int kc = idx / 96, r = idx % 96, nt = r >> 5, lane = r & 31;
                int nn = nt * 8 + (lane >> 2);
                int k0 = kc * 16 + (lane & 3) * 2;
                float w00 = W2[(k0 + 0) * MV + nn], w01 = W2[(k0 + 1) * MV + nn];
                float w10 = W2[(k0 + 8) * MV + nn], w11 = W2[(k0 + 9) * MV + nn];
                uint4 o;
                o.x = pkbf(w00, w01);
                o.y = pkbf(w10, w11);
                o.z = pkbf(bfres(w00), bfres(w01));
                o.w = pkbf(bfres(w10), bfres(w11));
                g_b2frag[idx] = o;
            }
        } else {
            for (int v = tid; v <= B; v += 256) {
                int lo = 0, hi = n;
                while (lo < hi) {
                    int mid = (lo + hi) >> 1;
                    if (batch[mid] < v) lo = mid + 1; else hi = mid;
                }
                g_segStart[v] = lo;
            }
        }
    }
}

// ---------------------------------------------------------------------------
// k_mlp: one CTA = 128 slots = 2 batches, 256 threads (8 warps).
// Warps 0/1 scan their batch segment for the first 64 cubes (ballot ranks),
// then all stage gathered node features as packed bf16 hi/lo in smem,
// then each warp computes a 16-slot x 128-h HMMA tile (3-pass split),
// converts C-frags to layer-2 A-frags in registers, runs layer-2 HMMA,
// and writes masked logits.
// ---------------------------------------------------------------------------
#define AHI_OFF 0
#define ALO_OFF 34816
#define HG_OFF  69632
#define SEL_OFF 70656
#define VC_OFF  71168
#define B2_OFF  71200
#define DSMEM_BYTES 71296

__global__ __launch_bounds__(256) void k_mlp(
    const float* __restrict__ nf, const float* __restrict__ b2,
    const unsigned char* __restrict__ cmb, const int* __restrict__ cmi,
    const unsigned char* __restrict__ mvb, const int* __restrict__ mvi,
    float* __restrict__ out, int Btot) {
    extern __shared__ unsigned char dsm[];
    uint32_t* s_ahi = (uint32_t*)(dsm + AHI_OFF);   // [128][68] packed bf16 hi pairs
    uint32_t* s_alo = (uint32_t*)(dsm + ALO_OFF);   // [128][68] lo pairs
    float*    s_hg  = (float*)(dsm + HG_OFF);       // [2][128]
    int*      s_sel = (int*)(dsm + SEL_OFF);        // [128]
    int*      s_vc  = (int*)(dsm + VC_OFF);         // [2]
    float*    s_b2  = (float*)(dsm + B2_OFF);       // [24]

    int tid = threadIdx.x, lane = tid & 31, w = tid >> 5;
    int slot0 = blockIdx.x * 128;
    int b0 = slot0 >> 6;
    int isb = g_maskIsBool[0], isb2 = g_maskIsBool[1];

    // ---- select (warps 0,1) + small staging (warps 2+) ----
    if (w < 2) {
        int b = b0 + w;
        int base = 0;
        if (b < Btot) {
            int start = g_segStart[b], end = g_segStart[b + 1];
            int it = start;
            int c = 0;
            if (it < end) {
                int i0 = it + lane;
                c = (i0 < end) ? (isb ? (cmb[i0] != 0) : (cmi[i0] != 0)) : 0;
            }
            while (it < end) {
                int nit = it + 32, nc = 0;
                if (nit < end) {                 // lookahead strip
                    int ni = nit + lane;
                    nc = (ni < end) ? (isb ? (cmb[ni] != 0) : (cmi[ni] != 0)) : 0;
                }
                unsigned mm = __ballot_sync(0xffffffffu, c);
                if (c) {
                    int rank = base + __popc(mm & ((1u << lane) - 1u));
                    if (rank < MC) s_sel[w * MC + rank] = it + lane;
                }
                base += __popc(mm);
                if (base >= MC) break;
                it = nit; c = nc;
            }
        }
        if (lane == 0) s_vc[w] = base < MC ? base : MC;
    } else {
        int t = tid - 64;     // 0..191
        if (t < 2 * H) s_hg[t] = g_hg[b0 * H + t];
        if (t < MV) s_b2[t] = b2[t];
    }
    __syncthreads();

    // ---- stage gathered node features as packed bf16 hi/lo ----
    {
        int vc0 = s_vc[0], vc1 = s_vc[1];
        for (int i = tid; i < 4096; i += 256) {     // 128 slots x 32 float4
            int s = i >> 5, q = i & 31;
            int cidx = s & 63, vc = (s >> 6) ? vc1 : vc0;
            float4 v = make_float4(0.f, 0.f, 0.f, 0.f);
            if (cidx < vc) {
                long long node = s_sel[s];
                v = *(const float4*)&nf[node * D + q * 4];
            }
            uint2 hi, lo;
            hi.x = pkbf(v.x, v.y);          hi.y = pkbf(v.z, v.w);
            lo.x = pkbf(bfres(v.x), bfres(v.y)); lo.y = pkbf(bfres(v.z), bfres(v.w));
            *(uint2*)&s_ahi[s * 68 + q * 2] = hi;
            *(uint2*)&s_alo[s * 68 + q * 2] = lo;
        }
    }
    __syncthreads();

    // ---- layer 1: per warp 16 slots x 128 h, 3-pass bf16 HMMA ----
    int r1 = w * 16 + (lane >> 2);         // local slot of c0/c1 rows
    int jb = lane & 3;
    float acc[16][4];
#pragma unroll
    for (int nt = 0; nt < 16; nt++)
#pragma unroll
        for (int j = 0; j < 4; j++) acc[nt][j] = 0.f;

#pragma unroll 1
    for (int kc = 0; kc < 8; kc++) {
        int j0 = kc * 8 + jb;
        uint32_t ah0 = s_ahi[r1 * 68 + j0];
        uint32_t ah1 = s_ahi[(r1 + 8) * 68 + j0];
        uint32_t ah2 = s_ahi[r1 * 68 + j0 + 4];
        uint32_t ah3 = s_ahi[(r1 + 8) * 68 + j0 + 4];
        uint32_t al0 = s_alo[r1 * 68 + j0];
        uint32_t al1 = s_alo[(r1 + 8) * 68 + j0];
        uint32_t al2 = s_alo[r1 * 68 + j0 + 4];
        uint32_t al3 = s_alo[(r1 + 8) * 68 + j0 + 4];
        const uint4* bp = &g_b1frag[kc * 16 * 32 + lane];
#pragma unroll
        for (int nt = 0; nt < 16; nt++) {
            uint4 bb = bp[nt * 32];
            mma16816(acc[nt], ah0, ah1, ah2, ah3, bb.x, bb.y);   // hi*Whi
            mma16816(acc[nt], ah0, ah1, ah2, ah3, bb.z, bb.w);   // hi*Wlo
            mma16816(acc[nt], al0, al1, al2, al3, bb.x, bb.y);   // lo*Whi
        }
    }

    // ---- h = relu(acc + hg) -> layer-2 A-fragments (registers only) ----
    int sel = w >> 2;                      // batch within CTA
    int colb = jb * 2;
    float acc2[3][4];
#pragma unroll
    for (int nt = 0; nt < 3; nt++)
#pragma unroll
        for (int j = 0; j < 4; j++) acc2[nt][j] = 0.f;

#pragma unroll
    for (int kc = 0; kc < 8; kc++) {
        uint32_t ah[4], al[4];
#pragma unroll
        for (int half = 0; half < 2; half++) {
            int nt = 2 * kc + half;
            int col = nt * 8 + colb;
            float g0 = s_hg[sel * H + col], g1 = s_hg[sel * H + col + 1];
            float h0 = fmaxf(acc[nt][0] + g0, 0.f);
            float h1 = fmaxf(acc[nt][1] + g1, 0.f);
            float h2 = fmaxf(acc[nt][2] + g0, 0.f);
            float h3 = fmaxf(acc[nt][3] + g1, 0.f);
            ah[half * 1 + 0 + half]     = 0;  // placeholder overwritten below
            // a0/a2: rows r1 (c0,c1); a1/a3: rows r1+8 (c2,c3)
            ah[half ? 2 : 0] = pkbf(h0, h1);
            ah[half ? 3 : 1] = pkbf(h2, h3);
            al[half ? 2 : 0] = pkbf(bfres(h0), bfres(h1));
            al[half ? 3 : 1] = pkbf(bfres(h2), bfres(h3));
        }
        const uint4* bp = &g_b2frag[kc * 3 * 32 + lane];
#pragma unroll
        for (int nt = 0; nt < 3; nt++) {
            uint4 bb = bp[nt * 32];
            mma16816(acc2[nt], ah[0], ah[1], ah[2], ah[3], bb.x, bb.y);
            mma16816(acc2[nt], ah[0], ah[1], ah[2], ah[3], bb.z, bb.w);
            mma16816(acc2[nt], al[0], al[1], al[2], al[3], bb.x, bb.y);
        }
    }

    // ---- masked epilogue: rows = slots r1, r1+8; cols = moves ----
    {
        int vc = s_vc[sel];
        int cA = r1 & 63;                  // cube idx within batch (rows r1)
        int slotA = slot0 + r1;
        int slotB = slotA + 8;
        int valA = cA < vc, valB = (cA + 8) < vc;
#pragma unroll
        for (int nt = 0; nt < 3; nt++) {
            int m0 = nt * 8 + colb;
            float bz0 = s_b2[m0], bz1 = s_b2[m0 + 1];
            long long oA = (long long)slotA * MV + m0;
            long long oB = (long long)slotB * MV + m0;
            int kA0 = isb2 ? (mvb[oA] != 0)     : (mvi[oA] != 0);
            int kA1 = isb2 ? (mvb[oA + 1] != 0) : (mvi[oA + 1] != 0);
            int kB0 = isb2 ? (mvb[oB] != 0)     : (mvi[oB] != 0);
            int kB1 = isb2 ? (mvb[oB + 1] != 0) : (mvi[oB + 1] != 0);
            float2 vA, vB;
            vA.x = (valA && kA0) ? acc2[nt][0] + bz0 : NEGV;
            vA.y = (valA && kA1) ? acc2[nt][1] + bz1 : NEGV;
            vB.x = (valB && kB0) ? acc2[nt][2] + bz0 : NEGV;
            vB.y = (valB && kB1) ? acc2[nt][3] + bz1 : NEGV;
            *(float2*)&out[oA] = vA;
            *(float2*)&out[oB] = vB;
        }
    }
}

// ---------------------------------------------------------------------------
extern "C" void kernel_launch(void* const* d_in, const int* in_sizes, int n_in,
                              void* d_out, int out_size) {
    const float* nf = (const float*)d_in[0];
    const float* gf = (const float*)d_in[1];
    const float* W1 = (const float*)d_in[2];
    const float* b1 = (const float*)d_in[3];
    const float* W2 = (const float*)d_in[4];
    const float* b2 = (const float*)d_in[5];
    const void* cm = d_in[6];
    const int* batch = (const int*)d_in[7];
    const void* mv = d_in[8];

    int n = in_sizes[7];
    int B = in_sizes[1] / G;
    if (B > MAXB) B = MAXB;

    cudaFuncSetAttribute(k_mlp, cudaFuncAttributeMaxDynamicSharedMemorySize,
                         DSMEM_BYTES);

    k_prep<<<B + 19, 256>>>(gf, W1, b1, W2,
                            (const unsigned char*)cm, (const unsigned char*)mv,
                            batch, n, B);
    k_mlp<<<(B + 1) / 2, 256, DSMEM_BYTES>>>(
        nf, b2,
        (const unsigned char*)cm, (const int*)cm,
        (const unsigned char*)mv, (const int*)mv,
        (float*)d_out, B);
}